// round 1
// baseline (speedup 1.0000x reference)
#include <cuda_runtime.h>
#include <cstdint>

#define NODE_EMB 128
#define EDGE_EMB 16
#define D_IN     160      // 128 + 2*16
#define N_MAX    100000

#define TILE_N   64
#define THREADS  256

// Scratch: scatter-mean accumulators (device globals — no cudaMalloc allowed)
__device__ float g_rec [N_MAX * EDGE_EMB];
__device__ float g_sent[N_MAX * EDGE_EMB];
__device__ float g_rcnt[N_MAX];
__device__ float g_scnt[N_MAX];

// ---------------- packed f32x2 helpers (sm_100+) ----------------
__device__ __forceinline__ unsigned long long pack2(float lo, float hi) {
    unsigned long long r;
    asm("mov.b64 %0, {%1, %2};" : "=l"(r) : "f"(lo), "f"(hi));
    return r;
}
__device__ __forceinline__ unsigned long long bcast2(float v) {
    unsigned long long r;
    asm("mov.b64 %0, {%1, %1};" : "=l"(r) : "f"(v));
    return r;
}
__device__ __forceinline__ void fma2(unsigned long long& d,
                                     unsigned long long a,
                                     unsigned long long b) {
    asm("fma.rn.f32x2 %0, %1, %2, %0;" : "+l"(d) : "l"(a), "l"(b));
}
__device__ __forceinline__ void unpack2(unsigned long long v, float& lo, float& hi) {
    asm("mov.b64 {%0, %1}, %2;" : "=f"(lo), "=f"(hi) : "l"(v));
}

// ---------------- kernel 1: zero accumulators ----------------
__global__ void zero_kernel(int N) {
    int stride = gridDim.x * blockDim.x;
    int t = blockIdx.x * blockDim.x + threadIdx.x;
    int total4 = N * EDGE_EMB / 4;          // N*4 float4's per array
    float4 z = make_float4(0.f, 0.f, 0.f, 0.f);
    for (int i = t; i < total4; i += stride) {
        reinterpret_cast<float4*>(g_rec)[i]  = z;
        reinterpret_cast<float4*>(g_sent)[i] = z;
    }
    for (int i = t; i < N; i += stride) {
        g_rcnt[i] = 0.f;
        g_scnt[i] = 0.f;
    }
}

// ---------------- kernel 2: fused dual scatter-sum + degree counts ----------------
// One thread per (edge, quad): reads float4 of edge_attr, vector-reduces into
// both rec (by row) and sent (by col) accumulators.
__global__ void scatter_kernel(const float4* __restrict__ edge_attr4,
                               const int* __restrict__ edge_index,
                               int E) {
    int t = blockIdx.x * blockDim.x + threadIdx.x;
    int total = E * 4;
    if (t >= total) return;
    int e = t >> 2;
    int q = t & 3;
    float4 v = edge_attr4[t];
    int row = edge_index[e];        // receiver
    int col = edge_index[E + e];    // sender
    float* pr = &g_rec [row * EDGE_EMB + q * 4];
    float* ps = &g_sent[col * EDGE_EMB + q * 4];
    asm volatile("red.global.add.v4.f32 [%0], {%1, %2, %3, %4};"
                 :: "l"(pr), "f"(v.x), "f"(v.y), "f"(v.z), "f"(v.w) : "memory");
    asm volatile("red.global.add.v4.f32 [%0], {%1, %2, %3, %4};"
                 :: "l"(ps), "f"(v.x), "f"(v.y), "f"(v.z), "f"(v.w) : "memory");
    if (q == 0) {
        atomicAdd(&g_rcnt[row], 1.0f);
        atomicAdd(&g_scnt[col], 1.0f);
    }
}

// ---------------- kernel 3: fused concat + MLP ----------------
// Block: 256 threads, TILE_N=64 nodes.
// Thread (ty = warp 0..7, tx = lane 0..31): 8 nodes x 4 cols register tile,
// accumulated as f32x2 pairs (2x fp32 FMA rate vs 3-reg FFMA on sm_103a).
// Shared: A-tile [64][160] (reused for h [64][128]), W1 [160][128], W2 [128][128].
__global__ __launch_bounds__(THREADS, 1)
void mlp_kernel(const float* __restrict__ x,
                const float* __restrict__ W1,
                const float* __restrict__ b1,
                const float* __restrict__ W2,
                const float* __restrict__ b2,
                float* __restrict__ out,
                int N) {
    extern __shared__ float smem[];
    float* As  = smem;                              // 64*160 = 10240 floats
    float* W1s = smem + TILE_N * D_IN;              // 160*128 = 20480 floats
    float* W2s = W1s + D_IN * NODE_EMB;             // 128*128 = 16384 floats

    int tid = threadIdx.x;
    int tx = tid & 31;    // col group -> cols [tx*4, tx*4+4)
    int ty = tid >> 5;    // node group -> nodes [ty*8, ty*8+8)
    int node0 = blockIdx.x * TILE_N;

    // Cooperative weight loads (L2-resident after first wave)
    for (int i = tid; i < (D_IN * NODE_EMB) / 4; i += THREADS)
        reinterpret_cast<float4*>(W1s)[i] = reinterpret_cast<const float4*>(W1)[i];
    for (int i = tid; i < (NODE_EMB * NODE_EMB) / 4; i += THREADS)
        reinterpret_cast<float4*>(W2s)[i] = reinterpret_cast<const float4*>(W2)[i];

    // Stage A-tile: concat(x, rec_mean, sent_mean)
    for (int idx = tid; idx < TILE_N * D_IN; idx += THREADS) {
        int nl = idx / D_IN;
        int k  = idx - nl * D_IN;
        int n  = node0 + nl;
        float v = 0.f;
        if (n < N) {
            if (k < NODE_EMB) {
                v = x[(size_t)n * NODE_EMB + k];
            } else if (k < NODE_EMB + EDGE_EMB) {
                float c = g_rcnt[n];
                v = g_rec[n * EDGE_EMB + (k - NODE_EMB)] / fmaxf(c, 1.f);
            } else {
                float c = g_scnt[n];
                v = g_sent[n * EDGE_EMB + (k - NODE_EMB - EDGE_EMB)] / fmaxf(c, 1.f);
            }
        }
        As[idx] = v;
    }
    __syncthreads();

    // ---- Phase 1: h = A @ W1 + b1, LeakyReLU ----
    unsigned long long acc[8][2];
    {
        float4 bv = *reinterpret_cast<const float4*>(&b1[tx * 4]);
        unsigned long long b01 = pack2(bv.x, bv.y);
        unsigned long long b23 = pack2(bv.z, bv.w);
        #pragma unroll
        for (int i = 0; i < 8; ++i) { acc[i][0] = b01; acc[i][1] = b23; }
    }
    #pragma unroll 4
    for (int k = 0; k < D_IN; ++k) {
        ulonglong2 b = *reinterpret_cast<const ulonglong2*>(&W1s[k * NODE_EMB + tx * 4]);
        #pragma unroll
        for (int i = 0; i < 8; ++i) {
            unsigned long long a2 = bcast2(As[(ty * 8 + i) * D_IN + k]);
            fma2(acc[i][0], a2, b.x);
            fma2(acc[i][1], a2, b.y);
        }
    }
    __syncthreads();   // everyone done reading As before overwrite

    // LeakyReLU, write h into As region as [64][128]
    #pragma unroll
    for (int i = 0; i < 8; ++i) {
        float h0, h1, h2, h3;
        unpack2(acc[i][0], h0, h1);
        unpack2(acc[i][1], h2, h3);
        h0 = (h0 >= 0.f) ? h0 : 0.01f * h0;
        h1 = (h1 >= 0.f) ? h1 : 0.01f * h1;
        h2 = (h2 >= 0.f) ? h2 : 0.01f * h2;
        h3 = (h3 >= 0.f) ? h3 : 0.01f * h3;
        float4 hv = make_float4(h0, h1, h2, h3);
        *reinterpret_cast<float4*>(&As[(ty * 8 + i) * NODE_EMB + tx * 4]) = hv;
    }
    __syncthreads();

    // ---- Phase 2: out = h @ W2 + b2 ----
    {
        float4 bv = *reinterpret_cast<const float4*>(&b2[tx * 4]);
        unsigned long long b01 = pack2(bv.x, bv.y);
        unsigned long long b23 = pack2(bv.z, bv.w);
        #pragma unroll
        for (int i = 0; i < 8; ++i) { acc[i][0] = b01; acc[i][1] = b23; }
    }
    #pragma unroll 4
    for (int k = 0; k < NODE_EMB; ++k) {
        ulonglong2 b = *reinterpret_cast<const ulonglong2*>(&W2s[k * NODE_EMB + tx * 4]);
        #pragma unroll
        for (int i = 0; i < 8; ++i) {
            unsigned long long a2 = bcast2(As[(ty * 8 + i) * NODE_EMB + k]);
            fma2(acc[i][0], a2, b.x);
            fma2(acc[i][1], a2, b.y);
        }
    }

    #pragma unroll
    for (int i = 0; i < 8; ++i) {
        int n = node0 + ty * 8 + i;
        if (n < N) {
            float o0, o1, o2, o3;
            unpack2(acc[i][0], o0, o1);
            unpack2(acc[i][1], o2, o3);
            float4 ov = make_float4(o0, o1, o2, o3);
            *reinterpret_cast<float4*>(&out[(size_t)n * NODE_EMB + tx * 4]) = ov;
        }
    }
}

// ---------------- launch ----------------
extern "C" void kernel_launch(void* const* d_in, const int* in_sizes, int n_in,
                              void* d_out, int out_size) {
    const float* x          = (const float*)d_in[0];
    const int*   edge_index = (const int*)  d_in[1];
    const float* edge_attr  = (const float*)d_in[2];
    const float* W1         = (const float*)d_in[3];
    const float* b1         = (const float*)d_in[4];
    const float* W2         = (const float*)d_in[5];
    const float* b2         = (const float*)d_in[6];
    float* out = (float*)d_out;

    int N = in_sizes[0] / NODE_EMB;
    int E = in_sizes[2] / EDGE_EMB;

    zero_kernel<<<256, 256>>>(N);

    int total = E * 4;
    scatter_kernel<<<(total + 255) / 256, 256>>>(
        reinterpret_cast<const float4*>(edge_attr), edge_index, E);

    const int smem_bytes = (TILE_N * D_IN + D_IN * NODE_EMB + NODE_EMB * NODE_EMB) * 4; // 188416
    cudaFuncSetAttribute(mlp_kernel, cudaFuncAttributeMaxDynamicSharedMemorySize, smem_bytes);
    mlp_kernel<<<(N + TILE_N - 1) / TILE_N, THREADS, smem_bytes>>>(
        x, W1, b1, W2, b2, out, N);
}

// round 2
// speedup vs baseline: 1.1726x; 1.1726x over previous
#include <cuda_runtime.h>
#include <cstdint>

#define NODE_EMB 128
#define EDGE_EMB 16
#define D_IN     160      // 128 + 2*16
#define N_MAX    100000

#define TILE_N   64
#define THREADS  512

// Scratch: scatter-mean accumulators (device globals — no cudaMalloc allowed)
__device__ float g_rec [N_MAX * EDGE_EMB];
__device__ float g_sent[N_MAX * EDGE_EMB];
__device__ float g_rcnt[N_MAX];
__device__ float g_scnt[N_MAX];

// ---------------- packed f32x2 helpers (sm_100+) ----------------
__device__ __forceinline__ unsigned long long pack2(float lo, float hi) {
    unsigned long long r;
    asm("mov.b64 %0, {%1, %2};" : "=l"(r) : "f"(lo), "f"(hi));
    return r;
}
__device__ __forceinline__ unsigned long long bcast2(float v) {
    unsigned long long r;
    asm("mov.b64 %0, {%1, %1};" : "=l"(r) : "f"(v));
    return r;
}
__device__ __forceinline__ void fma2(unsigned long long& d,
                                     unsigned long long a,
                                     unsigned long long b) {
    asm("fma.rn.f32x2 %0, %1, %2, %0;" : "+l"(d) : "l"(a), "l"(b));
}
__device__ __forceinline__ void unpack2(unsigned long long v, float& lo, float& hi) {
    asm("mov.b64 {%0, %1}, %2;" : "=f"(lo), "=f"(hi) : "l"(v));
}

// ---------------- kernel 1: zero accumulators ----------------
__global__ void zero_kernel(int N) {
    int stride = gridDim.x * blockDim.x;
    int t = blockIdx.x * blockDim.x + threadIdx.x;
    int total4 = N * EDGE_EMB / 4;          // N*4 float4's per array
    float4 z = make_float4(0.f, 0.f, 0.f, 0.f);
    for (int i = t; i < total4; i += stride) {
        reinterpret_cast<float4*>(g_rec)[i]  = z;
        reinterpret_cast<float4*>(g_sent)[i] = z;
    }
    for (int i = t; i < N; i += stride) {
        g_rcnt[i] = 0.f;
        g_scnt[i] = 0.f;
    }
}

// ---------------- kernel 2: fused dual scatter-sum + degree counts ----------------
// (unchanged from R1 — control for this round's A/B decomposition)
__global__ void scatter_kernel(const float4* __restrict__ edge_attr4,
                               const int* __restrict__ edge_index,
                               int E) {
    int t = blockIdx.x * blockDim.x + threadIdx.x;
    int total = E * 4;
    if (t >= total) return;
    int e = t >> 2;
    int q = t & 3;
    float4 v = edge_attr4[t];
    int row = edge_index[e];        // receiver
    int col = edge_index[E + e];    // sender
    float* pr = &g_rec [row * EDGE_EMB + q * 4];
    float* ps = &g_sent[col * EDGE_EMB + q * 4];
    asm volatile("red.global.add.v4.f32 [%0], {%1, %2, %3, %4};"
                 :: "l"(pr), "f"(v.x), "f"(v.y), "f"(v.z), "f"(v.w) : "memory");
    asm volatile("red.global.add.v4.f32 [%0], {%1, %2, %3, %4};"
                 :: "l"(ps), "f"(v.x), "f"(v.y), "f"(v.z), "f"(v.w) : "memory");
    if (q == 0) {
        atomicAdd(&g_rcnt[row], 1.0f);
        atomicAdd(&g_scnt[col], 1.0f);
    }
}

// ---------------- kernel 3: fused concat + MLP (v2) ----------------
// Block: 512 threads (16 warps = 4/SMSP for latency hiding), TILE_N=64 nodes.
// Thread (ty = warp 0..15 -> 4 nodes, tx = lane -> 4 cols).
// A staged in SMEM as pre-duplicated f32x2 pairs {v,v} so the inner loop is
// pure LDS.64(broadcast) + LDS.128 + FFMA2 — fma-pipe-bound by design.
// SMEM: A-dup ull[64*160] (80KB, reused for h-dup [64][128] = 64KB),
//       W1 float[160*128] (80KB), W2 float[128*128] (64KB) -> 229376 B.
__global__ __launch_bounds__(THREADS, 1)
void mlp_kernel(const float* __restrict__ x,
                const float* __restrict__ W1,
                const float* __restrict__ b1,
                const float* __restrict__ W2,
                const float* __restrict__ b2,
                float* __restrict__ out,
                int N) {
    extern __shared__ unsigned long long smem_u64[];
    unsigned long long* Ad = smem_u64;                          // 64*160 ull
    float* W1s = reinterpret_cast<float*>(Ad + TILE_N * D_IN);  // 160*128 f
    float* W2s = W1s + D_IN * NODE_EMB;                         // 128*128 f

    int tid = threadIdx.x;
    int tx = tid & 31;    // col group -> cols [tx*4, tx*4+4)
    int ty = tid >> 5;    // warp -> nodes [ty*4, ty*4+4)
    int node0 = blockIdx.x * TILE_N;

    // Cooperative weight loads (L2-resident after first wave)
    for (int i = tid; i < (D_IN * NODE_EMB) / 4; i += THREADS)
        reinterpret_cast<float4*>(W1s)[i] = reinterpret_cast<const float4*>(W1)[i];
    for (int i = tid; i < (NODE_EMB * NODE_EMB) / 4; i += THREADS)
        reinterpret_cast<float4*>(W2s)[i] = reinterpret_cast<const float4*>(W2)[i];

    // Stage A-tile: concat(x, rec_mean, sent_mean), duplicated {v,v}
    for (int idx = tid; idx < TILE_N * D_IN; idx += THREADS) {
        int nl = idx / D_IN;
        int k  = idx - nl * D_IN;
        int n  = node0 + nl;
        float v = 0.f;
        if (n < N) {
            if (k < NODE_EMB) {
                v = x[(size_t)n * NODE_EMB + k];
            } else if (k < NODE_EMB + EDGE_EMB) {
                float c = g_rcnt[n];
                v = g_rec[n * EDGE_EMB + (k - NODE_EMB)] / fmaxf(c, 1.f);
            } else {
                float c = g_scnt[n];
                v = g_sent[n * EDGE_EMB + (k - NODE_EMB - EDGE_EMB)] / fmaxf(c, 1.f);
            }
        }
        Ad[idx] = bcast2(v);
    }
    __syncthreads();

    // ---- Phase 1: h = A @ W1 + b1, LeakyReLU ----
    unsigned long long acc[4][2];
    {
        float4 bv = *reinterpret_cast<const float4*>(&b1[tx * 4]);
        unsigned long long b01 = pack2(bv.x, bv.y);
        unsigned long long b23 = pack2(bv.z, bv.w);
        #pragma unroll
        for (int i = 0; i < 4; ++i) { acc[i][0] = b01; acc[i][1] = b23; }
    }
    #pragma unroll 8
    for (int k = 0; k < D_IN; ++k) {
        ulonglong2 w = *reinterpret_cast<const ulonglong2*>(&W1s[k * NODE_EMB + tx * 4]);
        #pragma unroll
        for (int i = 0; i < 4; ++i) {
            unsigned long long a2 = Ad[(ty * 4 + i) * D_IN + k];  // LDS.64 broadcast
            fma2(acc[i][0], a2, w.x);
            fma2(acc[i][1], a2, w.y);
        }
    }
    __syncthreads();   // everyone done reading Ad before overwrite

    // LeakyReLU, write h (duplicated pairs) into Ad region as [64][128]
    #pragma unroll
    for (int i = 0; i < 4; ++i) {
        float h0, h1, h2, h3;
        unpack2(acc[i][0], h0, h1);
        unpack2(acc[i][1], h2, h3);
        h0 = (h0 >= 0.f) ? h0 : 0.01f * h0;
        h1 = (h1 >= 0.f) ? h1 : 0.01f * h1;
        h2 = (h2 >= 0.f) ? h2 : 0.01f * h2;
        h3 = (h3 >= 0.f) ? h3 : 0.01f * h3;
        unsigned long long* hr = &Ad[(ty * 4 + i) * NODE_EMB + tx * 4];
        hr[0] = bcast2(h0);
        hr[1] = bcast2(h1);
        hr[2] = bcast2(h2);
        hr[3] = bcast2(h3);
    }
    __syncthreads();

    // ---- Phase 2: out = h @ W2 + b2 ----
    {
        float4 bv = *reinterpret_cast<const float4*>(&b2[tx * 4]);
        unsigned long long b01 = pack2(bv.x, bv.y);
        unsigned long long b23 = pack2(bv.z, bv.w);
        #pragma unroll
        for (int i = 0; i < 4; ++i) { acc[i][0] = b01; acc[i][1] = b23; }
    }
    #pragma unroll 8
    for (int k = 0; k < NODE_EMB; ++k) {
        ulonglong2 w = *reinterpret_cast<const ulonglong2*>(&W2s[k * NODE_EMB + tx * 4]);
        #pragma unroll
        for (int i = 0; i < 4; ++i) {
            unsigned long long a2 = Ad[(ty * 4 + i) * NODE_EMB + k];  // LDS.64 broadcast
            fma2(acc[i][0], a2, w.x);
            fma2(acc[i][1], a2, w.y);
        }
    }

    #pragma unroll
    for (int i = 0; i < 4; ++i) {
        int n = node0 + ty * 4 + i;
        if (n < N) {
            float o0, o1, o2, o3;
            unpack2(acc[i][0], o0, o1);
            unpack2(acc[i][1], o2, o3);
            float4 ov = make_float4(o0, o1, o2, o3);
            *reinterpret_cast<float4*>(&out[(size_t)n * NODE_EMB + tx * 4]) = ov;
        }
    }
}

// ---------------- launch ----------------
extern "C" void kernel_launch(void* const* d_in, const int* in_sizes, int n_in,
                              void* d_out, int out_size) {
    const float* x          = (const float*)d_in[0];
    const int*   edge_index = (const int*)  d_in[1];
    const float* edge_attr  = (const float*)d_in[2];
    const float* W1         = (const float*)d_in[3];
    const float* b1         = (const float*)d_in[4];
    const float* W2         = (const float*)d_in[5];
    const float* b2         = (const float*)d_in[6];
    float* out = (float*)d_out;

    int N = in_sizes[0] / NODE_EMB;
    int E = in_sizes[2] / EDGE_EMB;

    zero_kernel<<<1184, 256>>>(N);

    int total = E * 4;
    scatter_kernel<<<(total + 255) / 256, 256>>>(
        reinterpret_cast<const float4*>(edge_attr), edge_index, E);

    const int smem_bytes = (TILE_N * D_IN * 2 + D_IN * NODE_EMB + NODE_EMB * NODE_EMB) * 4; // 229376
    cudaFuncSetAttribute(mlp_kernel, cudaFuncAttributeMaxDynamicSharedMemorySize, smem_bytes);
    mlp_kernel<<<(N + TILE_N - 1) / TILE_N, THREADS, smem_bytes>>>(
        x, W1, b1, W2, b2, out, N);
}